// round 1
// baseline (speedup 1.0000x reference)
#include <cuda_runtime.h>

// GHMRankingLoss: single-pass fused loss + histogram + per-bin loss sums.
// result = (1/N) * sum_b  max(count_b,1)^-0.75 * sum_{i in bin b} loss_i
//
// Pipeline (3 launches, all graph-capturable, same stream):
//   1) init_k:  zero the global double accumulators (must re-zero per replay)
//   2) main_k:  grid-stride pass, per-lane private smem histograms, block
//               tree-reduce, one double atomicAdd per bin per block
//   3) final_k: 1 thread computes the weighted mean into d_out

#define BINS 10
#define NTHREADS 256
#define NBLOCKS 1184   // 8 blocks / SM on 148 SMs

__device__ double g_sum[BINS];   // per-bin loss sums
__device__ double g_cnt[BINS];   // per-bin counts

__global__ void ghm_init_k() {
    if (threadIdx.x < BINS) {
        g_sum[threadIdx.x] = 0.0;
        g_cnt[threadIdx.x] = 0.0;
    }
}

__device__ __forceinline__ void ghm_accum(float2* hist, int tid,
                                          float o1, float o2, float t) {
    float diff = o1 - o2;
    // loss = max(0, -t*diff + margin), margin = 0
    float loss = fmaxf(0.0f, -t * diff);
    // expected_sign = 2*t - 1  (note: t is +-1, so this is {1, -3})
    float es = fmaf(2.0f, t, -1.0f);
    float x  = -diff * es;
    // g = sigmoid(x)
    float g = 1.0f / (1.0f + __expf(-x));
    // bin = clip(floor(g*10), 0, 9); g >= 0 always, g may round to 1.0f
    int bi = (int)(g * 10.0f);
    bi = (bi > BINS - 1) ? (BINS - 1) : bi;
    // per-lane private slot: hist[bi*NTHREADS + tid] -> no atomics, no bank conflicts
    float2 h = hist[bi * NTHREADS + tid];
    h.x += loss;
    h.y += 1.0f;
    hist[bi * NTHREADS + tid] = h;
}

__global__ void __launch_bounds__(NTHREADS)
ghm_main_k(const float* __restrict__ o1,
           const float* __restrict__ o2,
           const float* __restrict__ tg,
           int n) {
    __shared__ float2 hist[BINS * NTHREADS];

    const int tid = threadIdx.x;

    // zero this block's histograms
    #pragma unroll
    for (int b = 0; b < BINS; b++)
        hist[b * NTHREADS + tid] = make_float2(0.0f, 0.0f);
    __syncthreads();

    const int n4 = n >> 2;
    const int gid = blockIdx.x * NTHREADS + tid;
    const int gstride = gridDim.x * NTHREADS;

    const float4* o1v = (const float4*)o1;
    const float4* o2v = (const float4*)o2;
    const float4* tgv = (const float4*)tg;

    for (int i = gid; i < n4; i += gstride) {
        float4 a = __ldg(o1v + i);
        float4 b = __ldg(o2v + i);
        float4 t = __ldg(tgv + i);
        ghm_accum(hist, tid, a.x, b.x, t.x);
        ghm_accum(hist, tid, a.y, b.y, t.y);
        ghm_accum(hist, tid, a.z, b.z, t.z);
        ghm_accum(hist, tid, a.w, b.w, t.w);
    }

    // scalar tail (n not multiple of 4)
    for (int i = (n4 << 2) + gid; i < n; i += gstride)
        ghm_accum(hist, tid, __ldg(o1 + i), __ldg(o2 + i), __ldg(tg + i));

    __syncthreads();

    // tree-reduce across the 256 lanes for all bins
    #pragma unroll
    for (int s = NTHREADS / 2; s >= 1; s >>= 1) {
        if (tid < s) {
            #pragma unroll
            for (int b = 0; b < BINS; b++) {
                float2 lo = hist[b * NTHREADS + tid];
                float2 hi = hist[b * NTHREADS + tid + s];
                lo.x += hi.x;
                lo.y += hi.y;
                hist[b * NTHREADS + tid] = lo;
            }
        }
        __syncthreads();
    }

    // one double atomic per bin per block (single-lane REDG, negligible)
    if (tid < BINS) {
        float2 h = hist[tid * NTHREADS];
        atomicAdd(&g_sum[tid], (double)h.x);
        atomicAdd(&g_cnt[tid], (double)h.y);
    }
}

__global__ void ghm_final_k(float* __restrict__ out, double inv_n) {
    if (threadIdx.x == 0 && blockIdx.x == 0) {
        double acc = 0.0;
        #pragma unroll
        for (int b = 0; b < BINS; b++) {
            double tot = g_cnt[b];
            if (tot < 1.0) tot = 1.0;            // clamp(min=1)
            acc += pow(tot, -0.75) * g_sum[b];   // w = tot^-alpha
        }
        out[0] = (float)(acc * inv_n);
    }
}

extern "C" void kernel_launch(void* const* d_in, const int* in_sizes, int n_in,
                              void* d_out, int out_size) {
    const float* o1 = (const float*)d_in[0];
    const float* o2 = (const float*)d_in[1];
    const float* tg = (const float*)d_in[2];
    float* out = (float*)d_out;
    int n = in_sizes[0];

    ghm_init_k<<<1, 32>>>();
    ghm_main_k<<<NBLOCKS, NTHREADS>>>(o1, o2, tg, n);
    ghm_final_k<<<1, 32>>>(out, 1.0 / (double)n);
}